// round 16
// baseline (speedup 1.0000x reference)
#include <cuda_runtime.h>
#include <math_constants.h>
#include <cstdint>

#define NROWS 8192
#define IN_DIM 128
#define HID 256
#define SLOPE 0.01f
#define S_CONST 8192.0f

#define XP 133   // X smem pitch (words): (133*r + k) % 32 = (5r+k)%32, conflict-free frag loads
#define WP 35    // W smem pitch (words): (35*n + k) % 32 = (3n+k)%32, conflict-free frag loads
#define HP 130   // H smem pitch (words): float2-aligned stores/reads

// dynamic smem layout (words):
//   Xhi[32*XP] Xlo[32*XP] Whi[128*WP] Wlo[128*WP] Es[32*32] sred[128]
#define SMEM_WORDS (2 * 32 * XP + 2 * 128 * WP + 32 * 32 + 128)
#define SMEM_BYTES (SMEM_WORDS * 4)

// ---------------- scratch (__device__ globals; no allocs allowed) ----------
__device__ __align__(16) float g_Ppart[32 * 256 * HID];  // [r][kb][c] split-K partials (8 MB)
__device__ __align__(16) float g_v[NROWS];               // normalized flat[:8192]
__device__ __align__(16) float g_Upart[32 * IN_DIM];     // per-v-row partials of v^T X

__device__ __forceinline__ uint32_t f2tf(float x) {
    uint32_t r;
    asm("cvt.rna.tf32.f32 %0, %1;" : "=r"(r) : "f"(x));
    return r;
}

__device__ __forceinline__ void mma_tf32(float* d, const uint32_t* a, const uint32_t* b) {
    asm("mma.sync.aligned.m16n8k8.row.col.f32.tf32.tf32.f32 "
        "{%0,%1,%2,%3}, {%4,%5,%6,%7}, {%8,%9}, {%0,%1,%2,%3};"
        : "+f"(d[0]), "+f"(d[1]), "+f"(d[2]), "+f"(d[3])
        : "r"(a[0]), "r"(a[1]), "r"(a[2]), "r"(a[3]), "r"(b[0]), "r"(b[1]));
}

// ---------------- kernel A (fused): 3xTF32 tensor GEMM -> Ep partials ------
// grid 512 blocks: kb = bid>>1 (32-row chunk), ch = bid&1 (128-col half).
// 128 threads (4 warps). Warp w owns cols [w*32, w*32+32) of the half;
// each warp computes 2 m-tiles(16) x 4 n-tiles(8) via mma.m16n8k8.tf32,
// 3 MMAs per tile-k8 (hi*hi, hi*lo, lo*hi) for fp32-grade precision.
__global__ void __launch_bounds__(128) k_zhe(
        const float* __restrict__ X, const float* __restrict__ W,
        const float* __restrict__ b, const float* __restrict__ E,
        const float* __restrict__ Ai, const float* __restrict__ Aj) {
    extern __shared__ float smem[];
    uint32_t* const Xhi = (uint32_t*)smem;            // [32][XP]
    uint32_t* const Xlo = Xhi + 32 * XP;
    uint32_t* const Whi = Xlo + 32 * XP;              // [128][WP] (k-chunk of 32)
    uint32_t* const Wlo = Whi + 128 * WP;
    float*    const Es  = (float*)(Wlo + 128 * WP);   // [kk][r] 32x32
    float*    const sred = Es + 32 * 32;              // [128]
    float*    const Hs  = (float*)Whi;                // [32][HP], aliases Whi after mainloop

    const int t    = threadIdx.x;
    const int lane = t & 31;
    const int w    = t >> 5;                          // 0..3
    const int kb   = blockIdx.x >> 1;
    const int ch   = blockIdx.x & 1;
    const int r0   = kb * 32;                         // row base == E k-chunk base
    const int c0   = ch * 128;                        // column-half base
    const int qr   = lane >> 2;                       // 0..7
    const int qk   = lane & 3;                        // 0..3

    sred[t] = Ai[t] + Aj[t];

    {   // X tile: split into tf32 hi/lo, pitch XP
        const float4* X4 = (const float4*)(X + (size_t)r0 * IN_DIM);
        for (int i = t; i < 1024; i += 128) {
            int r = i >> 5, k4 = i & 31;
            float4 xv = X4[i];
            int base = r * XP + k4 * 4;
            uint32_t h;
            h = f2tf(xv.x); Xhi[base + 0] = h; Xlo[base + 0] = f2tf(xv.x - __uint_as_float(h));
            h = f2tf(xv.y); Xhi[base + 1] = h; Xlo[base + 1] = f2tf(xv.y - __uint_as_float(h));
            h = f2tf(xv.z); Xhi[base + 2] = h; Xlo[base + 2] = f2tf(xv.z - __uint_as_float(h));
            h = f2tf(xv.w); Xhi[base + 3] = h; Xlo[base + 3] = f2tf(xv.w - __uint_as_float(h));
        }
    }
    // E tile: rows 0..31, cols r0..r0+31, layout [kk][r]
    for (int i = t; i < 1024; i += 128) {
        int r = i & 31, kk = i >> 5;
        Es[kk * 32 + r] = E[(size_t)r * NROWS + r0 + kk];
    }
    __syncthreads();

    // finish s-reduction
    if (t < 64) sred[t] += sred[t + 64];
    __syncthreads();
    if (t < 32) {
        float x = sred[t] + sred[t + 32];
#pragma unroll
        for (int o = 16; o > 0; o >>= 1) x += __shfl_xor_sync(0xffffffffu, x, o);
        if (t == 0) sred[0] = x;
    }
    __syncthreads();
    const float s = sred[0];

    // ---- accumulators: 2 m-tiles x 4 n-tiles x 4 regs ----
    float d[2][4][4];
#pragma unroll
    for (int mt = 0; mt < 2; mt++)
#pragma unroll
        for (int nt = 0; nt < 4; nt++)
#pragma unroll
            for (int q = 0; q < 4; q++) d[mt][nt][q] = 0.f;

#pragma unroll 1
    for (int kc = 0; kc < 4; kc++) {
        // stage W k-chunk [kc*32, kc*32+32) split hi/lo (coalesced LDG)
        for (int i = t; i < 4096; i += 128) {
            int n = i >> 5, kl = i & 31;
            float wv = W[(size_t)(c0 + n) * IN_DIM + kc * 32 + kl];
            uint32_t h = f2tf(wv);
            Whi[n * WP + kl] = h;
            Wlo[n * WP + kl] = f2tf(wv - __uint_as_float(h));
        }
        __syncthreads();

#pragma unroll
        for (int k8 = 0; k8 < 32; k8 += 8) {
            // A fragments (hi/lo), 2 m-tiles
            uint32_t ahi[2][4], alo[2][4];
            const int acol = kc * 32 + k8 + qk;
#pragma unroll
            for (int mt = 0; mt < 2; mt++) {
                const int rA = (mt * 16 + qr) * XP;
                const int rB = (mt * 16 + qr + 8) * XP;
                ahi[mt][0] = Xhi[rA + acol];     alo[mt][0] = Xlo[rA + acol];
                ahi[mt][1] = Xhi[rB + acol];     alo[mt][1] = Xlo[rB + acol];
                ahi[mt][2] = Xhi[rA + acol + 4]; alo[mt][2] = Xlo[rA + acol + 4];
                ahi[mt][3] = Xhi[rB + acol + 4]; alo[mt][3] = Xlo[rB + acol + 4];
            }
            // B fragments (hi/lo), 4 n-tiles
            uint32_t bhi[4][2], blo[4][2];
            const int bk = k8 + qk;
#pragma unroll
            for (int nt = 0; nt < 4; nt++) {
                const int nb = (w * 32 + nt * 8 + qr) * WP;
                bhi[nt][0] = Whi[nb + bk];     blo[nt][0] = Wlo[nb + bk];
                bhi[nt][1] = Whi[nb + bk + 4]; blo[nt][1] = Wlo[nb + bk + 4];
            }
            // 3xTF32 MMAs
#pragma unroll
            for (int mt = 0; mt < 2; mt++)
#pragma unroll
                for (int nt = 0; nt < 4; nt++) {
                    mma_tf32(d[mt][nt], ahi[mt], bhi[nt]);
                    mma_tf32(d[mt][nt], ahi[mt], blo[nt]);
                    mma_tf32(d[mt][nt], alo[mt], bhi[nt]);
                }
        }
        __syncthreads();   // chunk consumed before restaging / Hs aliasing
    }

    // ---- activation; stage h into Hs (aliases Whi, pitch HP) ----
    {
#pragma unroll
        for (int mt = 0; mt < 2; mt++) {
#pragma unroll
            for (int nt = 0; nt < 4; nt++) {
                const int row  = mt * 16 + qr;
                const int coll = w * 32 + nt * 8 + 2 * qk;
                const float b0 = b[c0 + coll], b1 = b[c0 + coll + 1];
                float a0 = (d[mt][nt][0] + b0) * s;
                float a1 = (d[mt][nt][1] + b1) * s;
                float a2 = (d[mt][nt][2] + b0) * s;
                float a3 = (d[mt][nt][3] + b1) * s;
                a0 = a0 > 0.f ? a0 : SLOPE * a0;
                a1 = a1 > 0.f ? a1 : SLOPE * a1;
                a2 = a2 > 0.f ? a2 : SLOPE * a2;
                a3 = a3 > 0.f ? a3 : SLOPE * a3;
                *(float2*)&Hs[row * HP + coll]       = make_float2(__expf(a0), __expf(a1));
                *(float2*)&Hs[(row + 8) * HP + coll] = make_float2(__expf(a2), __expf(a3));
            }
        }
    }
    __syncthreads();

    // ---- Ep partial: thread t = column (0..127); all 32 E-rows ----
    float acc2[32];
#pragma unroll
    for (int j = 0; j < 32; j++) acc2[j] = 0.f;

#pragma unroll 4
    for (int kk = 0; kk < 32; kk++) {
        float h = Hs[kk * HP + t];               // consecutive lanes: conflict-free
        const float4* es4 = (const float4*)(Es + kk * 32);
#pragma unroll
        for (int j4 = 0; j4 < 8; j4++) {
            float4 e = es4[j4];
            acc2[j4 * 4 + 0] += e.x * h;
            acc2[j4 * 4 + 1] += e.y * h;
            acc2[j4 * 4 + 2] += e.z * h;
            acc2[j4 * 4 + 3] += e.w * h;
        }
    }
#pragma unroll
    for (int j = 0; j < 32; j++)
        g_Ppart[((size_t)j * 256 + kb) * HID + c0 + t] = acc2[j];
}

// ---------------- kernel B: reduce partials -> v; also partial of v^T X ----
// grid 32 blocks (one v-row each), 1024 threads
__global__ void k_v(const float* __restrict__ X) {
    __shared__ float sm[16][256];
    __shared__ float red[256];
    __shared__ float vsm[256];
    __shared__ float su[8][128];
    const int t = threadIdx.x;
    const int r = blockIdx.x;

    {   // phase 1: sum 256 kb-partials (contiguous, float4)
        const float4* P4 = (const float4*)(g_Ppart + (size_t)r * 256 * HID);
        const int c4 = t & 63, y = t >> 6;
        float4 a = make_float4(0.f, 0.f, 0.f, 0.f);
#pragma unroll
        for (int m = 0; m < 16; m++) {
            float4 p = P4[(size_t)(y + 16 * m) * 64 + c4];
            a.x += p.x; a.y += p.y; a.z += p.z; a.w += p.w;
        }
        sm[y][c4 * 4 + 0] = a.x;
        sm[y][c4 * 4 + 1] = a.y;
        sm[y][c4 * 4 + 2] = a.z;
        sm[y][c4 * 4 + 3] = a.w;
    }
    __syncthreads();

    float p = 0.f;
    if (t < 256) {
#pragma unroll
        for (int y = 0; y < 16; y++) p += sm[y][t];
        red[t] = p;
    }
    __syncthreads();
    if (t < 128) red[t] += red[t + 128];
    __syncthreads();
    if (t < 64)  red[t] += red[t + 64];
    __syncthreads();
    if (t < 32) {
        float x = red[t] + red[t + 32];
#pragma unroll
        for (int o = 16; o > 0; o >>= 1) x += __shfl_xor_sync(0xffffffffu, x, o);
        if (t == 0) red[0] = x;
    }
    __syncthreads();
    const float inv = 1.0f / red[0];
    if (t < 256) {
        float v = p * inv;
        vsm[t] = v;
        g_v[r * HID + t] = v;
    }
    __syncthreads();

    {   // phase 2: partial t_r[k] = sum_{c<256} v_c * X[256r + c][k]
        const int k = t & 127, jg = t >> 7;     // jg in [0,8)
        float acc = 0.f;
        const float* Xr = X + ((size_t)r * 256 + jg * 32) * IN_DIM + k;
#pragma unroll
        for (int jj = 0; jj < 32; jj++)
            acc += vsm[jg * 32 + jj] * Xr[(size_t)jj * IN_DIM];
        su[jg][k] = acc;
    }
    __syncthreads();
    if (t < 128) {
        float tot = 0.f;
#pragma unroll
        for (int g = 0; g < 8; g++) tot += su[g][t];
        g_Upart[r * IN_DIM + t] = tot;
    }
}

// ---------------- kernel C (fused): out blocks + alpha blocks --------------
// grid = 64 + 8192, 256 threads.
//   bid < 64   : redundant-w + softmax for 128 rows (hides under alpha's DRAM wall)
//   bid >= 64  : alpha[bid-64,:] = (v_i/S) * v  with streaming stores
__global__ void k_final(const float* __restrict__ W, const float* __restrict__ b,
                        float* __restrict__ out, float* __restrict__ alpha) {
    const int t = threadIdx.x;

    if (blockIdx.x < 64) {
        // ---- out path: recompute w from g_Upart (L2-cached), then softmax ----
        __shared__ __align__(16) float ts[128];
        __shared__ float ws[256];

        if (t < 128) {
            float a = 0.f;
#pragma unroll
            for (int rr = 0; rr < 32; rr++) a += g_Upart[rr * IN_DIM + t];
            ts[t] = a;
        }
        __syncthreads();

        {   // w[t] = dot(ts, W[t,:]) / S
            const float4* Wr = (const float4*)(W + (size_t)t * IN_DIM);
            const float4* t4 = (const float4*)ts;
            float d = 0.f;
#pragma unroll
            for (int i = 0; i < 32; i++) {
                float4 wv = Wr[i], tv = t4[i];
                d += wv.x * tv.x + wv.y * tv.y + wv.z * tv.z + wv.w * tv.w;
            }
            ws[t] = d * (1.0f / S_CONST);
        }
        __syncthreads();

        const int lane = t & 31, wid = t >> 5;
        const int rbase = blockIdx.x * 128 + wid * 16;

        float wl[8], bl[8];
#pragma unroll
        for (int q = 0; q < 8; q++) {
            wl[q] = ws[lane + 32 * q];
            bl[q] = b[lane + 32 * q];
        }

        for (int rr = 0; rr < 16; rr++) {
            const int i = rbase + rr;
            const float vi = g_v[i];
            float l[8];
            float m = -CUDART_INF_F;
#pragma unroll
            for (int q = 0; q < 8; q++) {
                l[q] = vi * wl[q] + bl[q];
                m = fmaxf(m, l[q]);
            }
#pragma unroll
            for (int o = 16; o > 0; o >>= 1) m = fmaxf(m, __shfl_xor_sync(0xffffffffu, m, o));
            float sum = 0.f;
#pragma unroll
            for (int q = 0; q < 8; q++) { l[q] = __expf(l[q] - m); sum += l[q]; }
#pragma unroll
            for (int o = 16; o > 0; o >>= 1) sum += __shfl_xor_sync(0xffffffffu, sum, o);
            const float inv = 1.0f / sum;
#pragma unroll
            for (int q = 0; q < 8; q++)
                out[(size_t)i * HID + lane + 32 * q] = l[q] * inv;
        }
    } else {
        // ---- alpha path: one row per block; streaming (evict-first) stores ----
        const int i = blockIdx.x - 64;
        const float a = g_v[i] * (1.0f / S_CONST);
        const float4* v4 = (const float4*)g_v;
        float4* o4 = (float4*)(alpha + (size_t)i * NROWS);
#pragma unroll
        for (int it = 0; it < 8; it++) {
            float4 vv = v4[t + 256 * it];
            __stwt(&o4[t + 256 * it],
                   make_float4(a * vv.x, a * vv.y, a * vv.z, a * vv.w));
        }
    }
}

// ---------------- launch ---------------------------------------------------
extern "C" void kernel_launch(void* const* d_in, const int* in_sizes, int n_in,
                              void* d_out, int out_size) {
    const float* X  = (const float*)d_in[0];
    const float* E  = (const float*)d_in[1];
    const float* W  = (const float*)d_in[2];
    const float* b  = (const float*)d_in[3];
    const float* Ai = (const float*)d_in[4];
    const float* Aj = (const float*)d_in[5];

    float* out   = (float*)d_out;                       // (8192, 256)
    float* alpha = out + (size_t)NROWS * HID;           // (8192, 8192)

    static bool attr_set = false;
    if (!attr_set) {
        cudaFuncSetAttribute(k_zhe, cudaFuncAttributeMaxDynamicSharedMemorySize,
                             SMEM_BYTES);
        attr_set = true;
    }

    k_zhe  <<<512, 128, SMEM_BYTES>>>(X, W, b, E, Ai, Aj);
    k_v    <<<32, 1024>>>(X);
    k_final<<<64 + NROWS, 256>>>(W, b, out, alpha);
}

// round 17
// speedup vs baseline: 1.3258x; 1.3258x over previous
#include <cuda_runtime.h>
#include <math_constants.h>
#include <cstdint>

#define NROWS 8192
#define IN_DIM 128
#define HID 256
#define SLOPE 0.01f
#define S_CONST 8192.0f

// ---------------- scratch (__device__ globals; no allocs allowed) ----------
__device__ __align__(16) float g_Ppart[32 * 256 * HID];  // [r][kb][c] split-K partials (8 MB)
__device__ __align__(16) float g_v[NROWS];               // normalized flat[:8192]
__device__ __align__(16) float g_Upart[32 * IN_DIM];     // per-v-row partials of v^T X

// ---------------- kernel A (fused): f32x2-packed GEMM -> Ep partials -------
// grid 512 blocks: kb = bid>>1 (32-row chunk), ch = bid&1 (128-col half).
// 256 threads; thread (ty,tx) owns 4 rows x cols {2tx,2tx+1,2tx+64,2tx+65}.
// Accumulators packed as f32x2 along column pairs; W LDS.64 loads ARE the
// packed operands; X stored DUPLICATED {x,x} so broadcast LDS.128 yields
// packed X operands for two k-steps. Mainloop: 32 FFMA2 + 16 LDS / kl-step.
__global__ void __launch_bounds__(256) k_zhe(
        const float* __restrict__ X, const float* __restrict__ W,
        const float* __restrict__ b, const float* __restrict__ E,
        const float* __restrict__ Ai, const float* __restrict__ Aj) {
    __shared__ float2 Xd[32 * 130];               // [row][k] duplicated, pitch 130 pairs
    __shared__ __align__(16) float Es[32][32];    // [kk][r]: broadcast float4 reads
    __shared__ __align__(16) float Ws[32 * 130];  // W chunk [k][col] pitch 130; Hs alias
    __shared__ float sred[128];
    float* const Hs = Ws;                         // aliases Ws after mainloop
    const int t  = threadIdx.x;
    const int tx = t & 31;
    const int ty = t >> 5;                        // 0..7 (constant per warp)
    const int kb = blockIdx.x >> 1;
    const int ch = blockIdx.x & 1;
    const int r0 = kb * 32;                       // row base == E k-chunk base
    const int c0 = ch * 128;                      // column-half base

    if (t < 128) sred[t] = Ai[t] + Aj[t];

    {   // X tile: duplicated {x,x} pairs, [row][k] pitch 130 float2
        const float4* X4 = (const float4*)(X + (size_t)r0 * IN_DIM);
        for (int i = t; i < 32 * 32; i += 256) {
            int r = i >> 5, k4 = i & 31;
            float4 xv = X4[i];
            float2* dst = &Xd[r * 130 + k4 * 4];
            dst[0] = make_float2(xv.x, xv.x);
            dst[1] = make_float2(xv.y, xv.y);
            dst[2] = make_float2(xv.z, xv.z);
            dst[3] = make_float2(xv.w, xv.w);
        }
    }
    // E tile: rows 0..31, cols r0..r0+31, layout [kk][r]
    for (int i = t; i < 32 * 32; i += 256) {
        int r = i & 31, kk = i >> 5;
        Es[kk][r] = E[(size_t)r * NROWS + r0 + kk];
    }
    __syncthreads();

    // finish s-reduction
    if (t < 64) sred[t] += sred[t + 64];
    __syncthreads();
    if (t < 32) {
        float x = sred[t] + sred[t + 32];
#pragma unroll
        for (int o = 16; o > 0; o >>= 1) x += __shfl_xor_sync(0xffffffffu, x, o);
        if (t == 0) sred[0] = x;
    }
    __syncthreads();
    const float s = sred[0];

    // ---- GEMM mainloop: accp[rr][0] = cols {2tx,2tx+1}; [1] = {+64,+65} ----
    unsigned long long accp[4][2];
#pragma unroll
    for (int rr = 0; rr < 4; rr++) { accp[rr][0] = 0ull; accp[rr][1] = 0ull; }

#pragma unroll 1
    for (int kc = 0; kc < 4; kc++) {
        {   // stage W chunk kc: [k_local][col] pitch 130 (coalesced LDG)
            const float* Wsrc = W + (size_t)c0 * IN_DIM + kc * 32 + tx;
#pragma unroll 4
            for (int col = ty; col < 128; col += 8)
                Ws[tx * 130 + col] = Wsrc[(size_t)col * IN_DIM];
        }
        __syncthreads();

        const float2* Xrow = Xd;
#pragma unroll 4
        for (int kl = 0; kl < 32; kl += 4) {
            // duplicated X: one LDS.128 = {x_k,x_k,x_{k+1},x_{k+1}} (broadcast)
            ulonglong2 xA[4], xB[4];
#pragma unroll
            for (int rr = 0; rr < 4; rr++) {
                const float2* xr = &Xrow[(ty * 4 + rr) * 130 + kc * 32];
                xA[rr] = *(const ulonglong2*)&xr[kl];
                xB[rr] = *(const ulonglong2*)&xr[kl + 2];
            }
#pragma unroll
            for (int kk = 0; kk < 4; kk++) {
                unsigned long long w0 = *(const unsigned long long*)&Ws[(kl + kk) * 130 + 2 * tx];
                unsigned long long w1 = *(const unsigned long long*)&Ws[(kl + kk) * 130 + 2 * tx + 64];
#pragma unroll
                for (int rr = 0; rr < 4; rr++) {
                    unsigned long long xk =
                        (kk == 0) ? xA[rr].x : (kk == 1) ? xA[rr].y
                      : (kk == 2) ? xB[rr].x : xB[rr].y;
                    asm("fma.rn.f32x2 %0, %1, %2, %0;"
                        : "+l"(accp[rr][0]) : "l"(xk), "l"(w0));
                    asm("fma.rn.f32x2 %0, %1, %2, %0;"
                        : "+l"(accp[rr][1]) : "l"(xk), "l"(w1));
                }
            }
        }
        __syncthreads();   // chunk consumed before restaging / Hs aliasing
    }

    // ---- activation; stage h into Hs (aliases Ws, pitch 130) ----
    {
        const int cl0 = 2 * tx, cl1 = 2 * tx + 64;
        float b0 = b[c0 + cl0], b1 = b[c0 + cl0 + 1];
        float b2 = b[c0 + cl1], b3 = b[c0 + cl1 + 1];
#pragma unroll
        for (int rr = 0; rr < 4; rr++) {
            const int row = ty * 4 + rr;
            float z0, z1, z2, z3;
            asm("mov.b64 {%0, %1}, %2;" : "=f"(z0), "=f"(z1) : "l"(accp[rr][0]));
            asm("mov.b64 {%0, %1}, %2;" : "=f"(z2), "=f"(z3) : "l"(accp[rr][1]));
            float a0 = (z0 + b0) * s;
            float a1 = (z1 + b1) * s;
            float a2 = (z2 + b2) * s;
            float a3 = (z3 + b3) * s;
            a0 = a0 > 0.f ? a0 : SLOPE * a0;
            a1 = a1 > 0.f ? a1 : SLOPE * a1;
            a2 = a2 > 0.f ? a2 : SLOPE * a2;
            a3 = a3 > 0.f ? a3 : SLOPE * a3;
            *(float2*)&Hs[row * 130 + cl0] = make_float2(__expf(a0), __expf(a1));
            *(float2*)&Hs[row * 130 + cl1] = make_float2(__expf(a2), __expf(a3));
        }
    }
    __syncthreads();

    // ---- Ep partial: thread t -> (col = t&127, row-half rh = t>>7) ----
    //   acc2[j] = sum_kk E[16rh+j][r0+kk] * h[kk][c0+col]
    const int col = t & 127;
    const int rh  = t >> 7;          // 0 or 1
    float acc2[16];
#pragma unroll
    for (int j = 0; j < 16; j++) acc2[j] = 0.f;

#pragma unroll 4
    for (int kk = 0; kk < 32; kk++) {
        float h = Hs[kk * 130 + col];            // consecutive lanes: conflict-free
        const float4* es4 = (const float4*)Es[kk] + rh * 4;
#pragma unroll
        for (int j4 = 0; j4 < 4; j4++) {
            float4 e = es4[j4];
            acc2[j4 * 4 + 0] += e.x * h;
            acc2[j4 * 4 + 1] += e.y * h;
            acc2[j4 * 4 + 2] += e.z * h;
            acc2[j4 * 4 + 3] += e.w * h;
        }
    }
#pragma unroll
    for (int j = 0; j < 16; j++)
        g_Ppart[((size_t)(rh * 16 + j) * 256 + kb) * HID + c0 + col] = acc2[j];
}

// ---------------- kernel B: reduce partials -> v; also partial of v^T X ----
// grid 32 blocks (one v-row each), 1024 threads
__global__ void k_v(const float* __restrict__ X) {
    __shared__ float sm[16][256];
    __shared__ float red[256];
    __shared__ float vsm[256];
    __shared__ float su[8][128];
    const int t = threadIdx.x;
    const int r = blockIdx.x;

    {   // phase 1: sum 256 kb-partials (contiguous, float4)
        const float4* P4 = (const float4*)(g_Ppart + (size_t)r * 256 * HID);
        const int c4 = t & 63, y = t >> 6;
        float4 a = make_float4(0.f, 0.f, 0.f, 0.f);
#pragma unroll
        for (int m = 0; m < 16; m++) {
            float4 p = P4[(size_t)(y + 16 * m) * 64 + c4];
            a.x += p.x; a.y += p.y; a.z += p.z; a.w += p.w;
        }
        sm[y][c4 * 4 + 0] = a.x;
        sm[y][c4 * 4 + 1] = a.y;
        sm[y][c4 * 4 + 2] = a.z;
        sm[y][c4 * 4 + 3] = a.w;
    }
    __syncthreads();

    float p = 0.f;
    if (t < 256) {
#pragma unroll
        for (int y = 0; y < 16; y++) p += sm[y][t];
        red[t] = p;
    }
    __syncthreads();
    if (t < 128) red[t] += red[t + 128];
    __syncthreads();
    if (t < 64)  red[t] += red[t + 64];
    __syncthreads();
    if (t < 32) {
        float x = red[t] + red[t + 32];
#pragma unroll
        for (int o = 16; o > 0; o >>= 1) x += __shfl_xor_sync(0xffffffffu, x, o);
        if (t == 0) red[0] = x;
    }
    __syncthreads();
    const float inv = 1.0f / red[0];
    if (t < 256) {
        float v = p * inv;
        vsm[t] = v;
        g_v[r * HID + t] = v;
    }
    __syncthreads();

    {   // phase 2: partial t_r[k] = sum_{c<256} v_c * X[256r + c][k]
        const int k = t & 127, jg = t >> 7;     // jg in [0,8)
        float acc = 0.f;
        const float* Xr = X + ((size_t)r * 256 + jg * 32) * IN_DIM + k;
#pragma unroll
        for (int jj = 0; jj < 32; jj++)
            acc += vsm[jg * 32 + jj] * Xr[(size_t)jj * IN_DIM];
        su[jg][k] = acc;
    }
    __syncthreads();
    if (t < 128) {
        float tot = 0.f;
#pragma unroll
        for (int g = 0; g < 8; g++) tot += su[g][t];
        g_Upart[r * IN_DIM + t] = tot;
    }
}

// ---------------- kernel C (fused): out blocks + alpha blocks --------------
// grid = 64 + 8192, 256 threads.
//   bid < 64   : redundant-w + softmax for 128 rows (hides under alpha's DRAM wall)
//   bid >= 64  : alpha[bid-64,:] = (v_i/S) * v
__global__ void k_final(const float* __restrict__ W, const float* __restrict__ b,
                        float* __restrict__ out, float* __restrict__ alpha) {
    const int t = threadIdx.x;

    if (blockIdx.x < 64) {
        // ---- out path: recompute w from g_Upart (L2-cached), then softmax ----
        __shared__ __align__(16) float ts[128];
        __shared__ float ws[256];

        if (t < 128) {
            float a = 0.f;
#pragma unroll
            for (int rr = 0; rr < 32; rr++) a += g_Upart[rr * IN_DIM + t];
            ts[t] = a;
        }
        __syncthreads();

        {   // w[t] = dot(ts, W[t,:]) / S
            const float4* Wr = (const float4*)(W + (size_t)t * IN_DIM);
            const float4* t4 = (const float4*)ts;
            float d = 0.f;
#pragma unroll
            for (int i = 0; i < 32; i++) {
                float4 wv = Wr[i], tv = t4[i];
                d += wv.x * tv.x + wv.y * tv.y + wv.z * tv.z + wv.w * tv.w;
            }
            ws[t] = d * (1.0f / S_CONST);
        }
        __syncthreads();

        const int lane = t & 31, wid = t >> 5;
        const int rbase = blockIdx.x * 128 + wid * 16;

        float wl[8], bl[8];
#pragma unroll
        for (int q = 0; q < 8; q++) {
            wl[q] = ws[lane + 32 * q];
            bl[q] = b[lane + 32 * q];
        }

        for (int rr = 0; rr < 16; rr++) {
            const int i = rbase + rr;
            const float vi = g_v[i];
            float l[8];
            float m = -CUDART_INF_F;
#pragma unroll
            for (int q = 0; q < 8; q++) {
                l[q] = vi * wl[q] + bl[q];
                m = fmaxf(m, l[q]);
            }
#pragma unroll
            for (int o = 16; o > 0; o >>= 1) m = fmaxf(m, __shfl_xor_sync(0xffffffffu, m, o));
            float sum = 0.f;
#pragma unroll
            for (int q = 0; q < 8; q++) { l[q] = __expf(l[q] - m); sum += l[q]; }
#pragma unroll
            for (int o = 16; o > 0; o >>= 1) sum += __shfl_xor_sync(0xffffffffu, sum, o);
            const float inv = 1.0f / sum;
#pragma unroll
            for (int q = 0; q < 8; q++)
                out[(size_t)i * HID + lane + 32 * q] = l[q] * inv;
        }
    } else {
        // ---- alpha path: one row per block ----
        const int i = blockIdx.x - 64;
        const float a = g_v[i] * (1.0f / S_CONST);
        const float4* v4 = (const float4*)g_v;
        float4* o4 = (float4*)(alpha + (size_t)i * NROWS);
#pragma unroll
        for (int it = 0; it < 8; it++) {
            float4 vv = v4[t + 256 * it];
            o4[t + 256 * it] = make_float4(a * vv.x, a * vv.y, a * vv.z, a * vv.w);
        }
    }
}

// ---------------- launch ---------------------------------------------------
extern "C" void kernel_launch(void* const* d_in, const int* in_sizes, int n_in,
                              void* d_out, int out_size) {
    const float* X  = (const float*)d_in[0];
    const float* E  = (const float*)d_in[1];
    const float* W  = (const float*)d_in[2];
    const float* b  = (const float*)d_in[3];
    const float* Ai = (const float*)d_in[4];
    const float* Aj = (const float*)d_in[5];

    float* out   = (float*)d_out;                       // (8192, 256)
    float* alpha = out + (size_t)NROWS * HID;           // (8192, 8192)

    k_zhe  <<<512, 256>>>(X, W, b, E, Ai, Aj);
    k_v    <<<32, 1024>>>(X);
    k_final<<<64 + NROWS, 256>>>(W, b, out, alpha);
}